// round 16
// baseline (speedup 1.0000x reference)
#include <cuda_runtime.h>
#include <cuda_fp16.h>
#include <cstdint>

#define HEADS 4
#define DIMH  32
#define NTOK  4096
#define CH    128
#define BATCH 4

// Scratch (allocation is forbidden in kernel_launch).
__device__ __align__(16) __half g_q[(size_t)BATCH * HEADS * NTOK * DIMH];  // [bh][n][32], pre-scaled dimh^-.5*log2e
__device__ __align__(16) __half g_k[(size_t)BATCH * HEADS * NTOK * DIMH];  // [bh][n][32]
__device__ __align__(16) __half g_v[(size_t)BATCH * HEADS * DIMH * NTOK];  // [bh][32][n] d-major
__device__ __align__(16) __half g_att[(size_t)BATCH * CH * NTOK];          // [b][128][n] d-major fp16
__device__ __align__(16) __half g_x[(size_t)BATCH * CH * NTOK];            // x in fp16
// Pre-converted weights (filled by w16_kernel each launch).
__device__ __align__(16) __half g_wqh[3 * CH * CH];   // w_qkv fp16 hi (q rows pre-scaled)
__device__ __align__(16) __half g_wvl[CH * CH];       // w_qkv V-group fp16 residual
__device__ __align__(16) __half g_pwh[CH * CH];       // w_out fp16 hi
__device__ __align__(16) __half g_pwl[CH * CH];       // w_out fp16 residual

// ---------------------------------------------------------------------------
__device__ __forceinline__ uint32_t packh(float lo, float hi) {
    uint32_t r; asm("cvt.rn.f16x2.f32 %0, %1, %2;" : "=r"(r) : "f"(hi), "f"(lo)); return r;
}
__device__ __forceinline__ uint32_t ex2h2(uint32_t x) {
    uint32_t y; asm("ex2.approx.f16x2 %0, %1;" : "=r"(y) : "r"(x)); return y;
}
__device__ __forceinline__ uint32_t hadd2(uint32_t a, uint32_t b) {
    uint32_t y; asm("add.rn.f16x2 %0, %1, %2;" : "=r"(y) : "r"(a), "r"(b)); return y;
}
__device__ __forceinline__ void unpackh2(float& lo, float& hi, uint32_t x) {
    asm("{.reg .f16 l,h; mov.b32 {l,h}, %2; cvt.f32.f16 %0, l; cvt.f32.f16 %1, h;}"
        : "=f"(lo), "=f"(hi) : "r"(x));
}
__device__ __forceinline__ uint32_t pack2h(__half a, __half b) {
    return (uint32_t)__half_as_ushort(a) | ((uint32_t)__half_as_ushort(b) << 16);
}
__device__ __forceinline__ uint32_t smem_u32(const void* p) {
    uint32_t a;
    asm("{ .reg .u64 t; cvta.to.shared.u64 t, %1; cvt.u32.u64 %0, t; }" : "=r"(a) : "l"(p));
    return a;
}
__device__ __forceinline__ void cpa16(uint32_t dst, const void* src) {
    asm volatile("cp.async.ca.shared.global [%0], [%1], 16;" :: "r"(dst), "l"(src));
}
#define CP_COMMIT() asm volatile("cp.async.commit_group;" ::: "memory")
#define CP_WAIT0()  asm volatile("cp.async.wait_group 0;" ::: "memory")
#define CP_WAIT1()  asm volatile("cp.async.wait_group 1;" ::: "memory")
__device__ __forceinline__ void ldsm2(uint32_t& a, uint32_t& b, uint32_t addr) {
    asm volatile("ldmatrix.sync.aligned.m8n8.x2.shared.b16 {%0,%1}, [%2];"
                 : "=r"(a), "=r"(b) : "r"(addr));
}
__device__ __forceinline__ void ldsm2t(uint32_t& a, uint32_t& b, uint32_t addr) {
    asm volatile("ldmatrix.sync.aligned.m8n8.x2.trans.shared.b16 {%0,%1}, [%2];"
                 : "=r"(a), "=r"(b) : "r"(addr));
}
// D += A*B, fp16 m16n8k16, fp32 accum
__device__ __forceinline__ void mma16h(float c[4], uint32_t a0, uint32_t a1,
                                       uint32_t a2, uint32_t a3,
                                       uint32_t b0, uint32_t b1) {
    asm volatile(
        "mma.sync.aligned.m16n8k16.row.col.f32.f16.f16.f32 "
        "{%0,%1,%2,%3}, {%4,%5,%6,%7}, {%8,%9}, {%0,%1,%2,%3};"
        : "+f"(c[0]), "+f"(c[1]), "+f"(c[2]), "+f"(c[3])
        : "r"(a0), "r"(a1), "r"(a2), "r"(a3), "r"(b0), "r"(b1));
}

// ---------------------------------------------------------------------------
// Kernel W: one-time conversions: w_qkv (q rows pre-scaled), w_out split,
// and x -> fp16. grid (2112), block 256. Flat chunk index.
// ---------------------------------------------------------------------------
__global__ __launch_bounds__(256) void w16_kernel(const float* __restrict__ x,
                                                  const float* __restrict__ wqkv,
                                                  const float* __restrict__ wout) {
    const int idx = blockIdx.x * 256 + threadIdx.x;   // float4 chunk index
    const float QSCALE = 0.17677669529663687f * 1.4426950408889634f;
    if (idx < 12288) {   // w_qkv: 384*128/4 chunks
        float4 v = *reinterpret_cast<const float4*>(wqkv + (size_t)idx * 4);
        const float s = (idx < 4096) ? QSCALE : 1.0f;   // q rows pre-scaled
        __half h0 = __float2half(v.x * s), h1 = __float2half(v.y * s);
        __half h2 = __float2half(v.z * s), h3 = __float2half(v.w * s);
        *reinterpret_cast<uint2*>(&g_wqh[(size_t)idx * 4]) =
            make_uint2(pack2h(h0, h1), pack2h(h2, h3));
        if (idx >= 8192) {   // V group rows 256..383: residual (scale 1)
            __half l0 = __float2half(v.x - __half2float(h0));
            __half l1 = __float2half(v.y - __half2float(h1));
            __half l2 = __float2half(v.z - __half2float(h2));
            __half l3 = __float2half(v.w - __half2float(h3));
            *reinterpret_cast<uint2*>(&g_wvl[(size_t)(idx - 8192) * 4]) =
                make_uint2(pack2h(l0, l1), pack2h(l2, l3));
        }
    } else if (idx < 16384) {  // w_out: 128*128/4 chunks
        const int j = idx - 12288;
        float4 v = *reinterpret_cast<const float4*>(wout + (size_t)j * 4);
        __half h0 = __float2half(v.x), h1 = __float2half(v.y);
        __half h2 = __float2half(v.z), h3 = __float2half(v.w);
        *reinterpret_cast<uint2*>(&g_pwh[(size_t)j * 4]) =
            make_uint2(pack2h(h0, h1), pack2h(h2, h3));
        __half l0 = __float2half(v.x - __half2float(h0));
        __half l1 = __float2half(v.y - __half2float(h1));
        __half l2 = __float2half(v.z - __half2float(h2));
        __half l3 = __float2half(v.w - __half2float(h3));
        *reinterpret_cast<uint2*>(&g_pwl[(size_t)j * 4]) =
            make_uint2(pack2h(l0, l1), pack2h(l2, l3));
    } else {             // x: 4*128*4096/4 = 524288 chunks
        const int j = idx - 16384;
        float4 v = *reinterpret_cast<const float4*>(x + (size_t)j * 4);
        *reinterpret_cast<uint2*>(&g_x[(size_t)j * 4]) =
            make_uint2(packh(v.x, v.y), packh(v.z, v.w));
    }
}

// ---------------------------------------------------------------------------
// Kernel A: fp16 tensor qkv; ALL staging via cp.async (W from g_wqh, X from
// g_x). TILE_N=64, grid (64,4), block 256, occ 2.
// ---------------------------------------------------------------------------
#define QW_STR 136
#define QX_STR 72
#define QKV_SMEM ((2 * 128 * QW_STR + 128 * QX_STR) * 2)   // 88064 B

__global__ __launch_bounds__(256, 2) void qkv_kernel() {
    extern __shared__ __half hsm[];
    __half* Wh = hsm;
    __half* Wl = hsm + 128 * QW_STR;
    __half* Xh = hsm + 2 * 128 * QW_STR;

    const int t = threadIdx.x;
    const int lane = t & 31, wid = t >> 5;
    const int g = lane >> 2, tg = lane & 3;
    const int rr = lane & 15;
    const int m0 = wid * 16;
    const int b = blockIdx.y;
    const int n0 = blockIdx.x * 64;

    const uint32_t wh_u = smem_u32(Wh);
    const uint32_t wl_u = smem_u32(Wl);
    const uint32_t xh_u0 = smem_u32(Xh);
    const int wrow = t >> 4, wc = t & 15;

    // Prologue: X tile (4/thread) + W group 0 (8/thread), all cp.async.
    const __half* xb = g_x + (size_t)b * CH * NTOK;
#pragma unroll
    for (int i = 0; i < 4; i++) {
        int e = t + i * 256, row = e >> 3, c = e & 7;
        cpa16(xh_u0 + (row * QX_STR + c * 8) * 2u, xb + (size_t)row * NTOK + n0 + c * 8);
    }
#pragma unroll
    for (int i = 0; i < 8; i++)
        cpa16(wh_u + ((wrow + 16 * i) * QW_STR + wc * 8) * 2u,
              g_wqh + (size_t)(wrow + 16 * i) * 128 + wc * 8);
    CP_COMMIT();

    const int o = m0 + g, o2 = m0 + 8 + g;
    const uint32_t xh_u = xh_u0 + rr * (QX_STR * 2);

    for (int grp = 0; grp < 3; grp++) {
        CP_WAIT0();
        __syncthreads();   // W[grp] + X ready

        float Sc[8][4];
#pragma unroll
        for (int nb = 0; nb < 8; nb++)
            Sc[nb][0] = Sc[nb][1] = Sc[nb][2] = Sc[nb][3] = 0.f;

#pragma unroll
        for (int kblk = 0; kblk < 8; kblk++) {
            const int kc = 16 * kblk + 2 * tg;
            uint32_t ah0 = *reinterpret_cast<const uint32_t*>(&Wh[o  * QW_STR + kc]);
            uint32_t ah1 = *reinterpret_cast<const uint32_t*>(&Wh[o2 * QW_STR + kc]);
            uint32_t ah2 = *reinterpret_cast<const uint32_t*>(&Wh[o  * QW_STR + kc + 8]);
            uint32_t ah3 = *reinterpret_cast<const uint32_t*>(&Wh[o2 * QW_STR + kc + 8]);
            uint32_t al0 = 0, al1 = 0, al2 = 0, al3 = 0;
            if (grp == 2) {
                al0 = *reinterpret_cast<const uint32_t*>(&Wl[o  * QW_STR + kc]);
                al1 = *reinterpret_cast<const uint32_t*>(&Wl[o2 * QW_STR + kc]);
                al2 = *reinterpret_cast<const uint32_t*>(&Wl[o  * QW_STR + kc + 8]);
                al3 = *reinterpret_cast<const uint32_t*>(&Wl[o2 * QW_STR + kc + 8]);
            }
#pragma unroll
            for (int nb = 0; nb < 8; nb++) {
                uint32_t b0, b1;
                ldsm2t(b0, b1, xh_u + kblk * (16 * QX_STR * 2) + nb * 16);
                mma16h(Sc[nb], ah0, ah1, ah2, ah3, b0, b1);
                if (grp == 2) mma16h(Sc[nb], al0, al1, al2, al3, b0, b1);
            }
        }

        __syncthreads();   // all warps done reading Wh/Wl
        if (grp < 2) {     // prefetch next group's W; lands during output stores
            const __half* wg = g_wqh + (size_t)(grp + 1) * 128 * 128;
#pragma unroll
            for (int i = 0; i < 8; i++)
                cpa16(wh_u + ((wrow + 16 * i) * QW_STR + wc * 8) * 2u,
                      wg + (size_t)(wrow + 16 * i) * 128 + wc * 8);
            if (grp == 1) {
#pragma unroll
                for (int i = 0; i < 8; i++)
                    cpa16(wl_u + ((wrow + 16 * i) * QW_STR + wc * 8) * 2u,
                          g_wvl + (size_t)(wrow + 16 * i) * 128 + wc * 8);
            }
            CP_COMMIT();
        }

        if (grp < 2) {
            __half* dst = grp ? g_k : g_q;   // q already pre-scaled via weights
            __half* r0 = dst + ((size_t)(b * HEADS + (o  >> 5)) * NTOK) * DIMH + (o  & 31);
            __half* r2 = dst + ((size_t)(b * HEADS + (o2 >> 5)) * NTOK) * DIMH + (o2 & 31);
#pragma unroll
            for (int nb = 0; nb < 8; nb++) {
                int n = n0 + 8 * nb + 2 * tg;
                r0[(size_t)n * DIMH]       = __float2half(Sc[nb][0]);
                r0[(size_t)(n + 1) * DIMH] = __float2half(Sc[nb][1]);
                r2[(size_t)n * DIMH]       = __float2half(Sc[nb][2]);
                r2[(size_t)(n + 1) * DIMH] = __float2half(Sc[nb][3]);
            }
        } else {
            __half* v0 = g_v + ((size_t)(b * HEADS + (o  >> 5)) * DIMH + (o  & 31)) * NTOK;
            __half* v2 = g_v + ((size_t)(b * HEADS + (o2 >> 5)) * DIMH + (o2 & 31)) * NTOK;
#pragma unroll
            for (int nb = 0; nb < 8; nb++) {
                int n = n0 + 8 * nb + 2 * tg;
                *reinterpret_cast<uint32_t*>(&v0[n]) = packh(Sc[nb][0], Sc[nb][1]);
                *reinterpret_cast<uint32_t*>(&v2[n]) = packh(Sc[nb][2], Sc[nb][3]);
            }
        }
    }
}

// ---------------------------------------------------------------------------
// Kernel B: fp16 flash attention, triple-buffer ring (1 barrier/tile).
// grid (16, 16), block 256, occ 2.
// ---------------------------------------------------------------------------
#define QK_STRIDE 40
#define VT_STRIDE 136
#define OT_STRIDE 132
#define QT_BYTES  (128 * QK_STRIDE * 2)
#define QS_BYTES  (2 * QT_BYTES)           // 20480
#define KS_BYTES  (128 * QK_STRIDE * 2)    // 10240
#define VT_BYTES  (DIMH * VT_STRIDE * 2)   // 8704
#define ATT_SMEM  (QS_BYTES + 3 * KS_BYTES + 3 * VT_BYTES)  // 77312

__global__ __launch_bounds__(256, 2) void attn_kernel() {
    extern __shared__ __align__(16) char dsm[];
    __half* Qs = reinterpret_cast<__half*>(dsm);
    __half* Ks = reinterpret_cast<__half*>(dsm + QS_BYTES);
    __half* Vt = reinterpret_cast<__half*>(dsm + QS_BYTES + 3 * KS_BYTES);

    const int t = threadIdx.x;
    const int lane = t & 31, wid = t >> 5;
    const int g = lane >> 2, tg = lane & 3;
    const int rr = lane & 15;
    const int m0 = wid * 16;
    const int bh = blockIdx.y;
    const int q0 = blockIdx.x << 8;

    const __half* qg = g_q + ((size_t)bh * NTOK + q0) * DIMH;
    const __half* kg = g_k + (size_t)bh * NTOK * DIMH;
    const __half* vg = g_v + (size_t)bh * DIMH * NTOK;

    const int kr0 = t >> 2, kc0 = t & 3;
    const int kr1 = (t + 256) >> 2, kc1 = t & 3;
    const int svr = t >> 4, svc = t & 15;
    const uint32_t ks_u = smem_u32(Ks);
    const uint32_t vt_u = smem_u32(Vt);
    const uint32_t kfrag = ks_u + (rr & 7) * (QK_STRIDE * 2) + (rr >> 3) * 16;
    const uint32_t vfrag = vt_u + (rr & 7) * (VT_STRIDE * 2) + (rr >> 3) * 16;

    // Prologue: stage tile 0 into ring slot 0.
    cpa16(ks_u + (kr0 * QK_STRIDE + kc0 * 8) * 2u, kg + (size_t)kr0 * DIMH + kc0 * 8);
    cpa16(ks_u + (kr1 * QK_STRIDE + kc1 * 8) * 2u, kg + (size_t)kr1 * DIMH + kc1 * 8);
#pragma unroll
    for (int k2 = 0; k2 < 2; k2++)
        cpa16(vt_u + ((svr + 16 * k2) * VT_STRIDE + svc * 8) * 2u,
              vg + (size_t)(svr + 16 * k2) * NTOK + svc * 8);
    CP_COMMIT();

    // Q: both tiles -> smem.
#pragma unroll
    for (int i = 0; i < 4; i++) {
        int idx = t + i * 256, row = idx >> 2, c = idx & 3;
        *reinterpret_cast<uint4*>(&Qs[row * QK_STRIDE + c * 8]) =
            *reinterpret_cast<const uint4*>(qg + (size_t)row * DIMH + c * 8);
    }
    __syncthreads();

    uint32_t qa[2][2][4];
#pragma unroll
    for (int qt = 0; qt < 2; qt++)
#pragma unroll
        for (int kblk = 0; kblk < 2; kblk++) {
            const __half* r0 = &Qs[(128 * qt + m0 + g)     * QK_STRIDE + 16 * kblk + 2 * tg];
            const __half* r1 = &Qs[(128 * qt + m0 + 8 + g) * QK_STRIDE + 16 * kblk + 2 * tg];
            qa[qt][kblk][0] = *reinterpret_cast<const uint32_t*>(r0);
            qa[qt][kblk][1] = *reinterpret_cast<const uint32_t*>(r1);
            qa[qt][kblk][2] = *reinterpret_cast<const uint32_t*>(r0 + 8);
            qa[qt][kblk][3] = *reinterpret_cast<const uint32_t*>(r1 + 8);
        }

    float Oc[2][4][4];
#pragma unroll
    for (int qt = 0; qt < 2; qt++)
#pragma unroll
        for (int db = 0; db < 4; db++)
#pragma unroll
            for (int i = 0; i < 4; i++) Oc[qt][db][i] = 0.f;
    float lsum[2][2] = {{0.f, 0.f}, {0.f, 0.f}};
    int buf = 0;

    for (int tile = 0; tile < 32; tile++) {
        // Prefetch tile+1 into ring slot (buf+1)%3 — that slot was last read
        // at tile-2; with one barrier per tile warp skew <= 1 tile => safe.
        if (tile < 31) {
            const int jn = (tile + 1) << 7;
            const int nb3 = (buf + 1 == 3) ? 0 : buf + 1;
            const uint32_t kd = ks_u + nb3 * KS_BYTES;
            const uint32_t vd = vt_u + nb3 * VT_BYTES;
            cpa16(kd + (kr0 * QK_STRIDE + kc0 * 8) * 2u, kg + (size_t)(jn + kr0) * DIMH + kc0 * 8);
            cpa16(kd + (kr1 * QK_STRIDE + kc1 * 8) * 2u, kg + (size_t)(jn + kr1) * DIMH + kc1 * 8);
#pragma unroll
            for (int k2 = 0; k2 < 2; k2++)
                cpa16(vd + ((svr + 16 * k2) * VT_STRIDE + svc * 8) * 2u,
                      vg + (size_t)(svr + 16 * k2) * NTOK + jn + svc * 8);
        }
        CP_COMMIT();
        CP_WAIT1();        // current tile's slot landed
        __syncthreads();   // single barrier per tile

        const uint32_t kcur = kfrag + buf * KS_BYTES;
        const uint32_t vcur = vfrag + buf * VT_BYTES;

#pragma unroll
        for (int c = 0; c < 8; c++) {
            const int nb0 = 2 * c, nb1 = nb0 + 1;
            uint32_t kb[2][2][2];
#pragma unroll
            for (int kblk = 0; kblk < 2; kblk++) {
                ldsm2(kb[0][kblk][0], kb[0][kblk][1], kcur + nb0 * (8 * QK_STRIDE * 2) + kblk * 32);
                ldsm2(kb[1][kblk][0], kb[1][kblk][1], kcur + nb1 * (8 * QK_STRIDE * 2) + kblk * 32);
            }
            uint32_t vb[4][2];
#pragma unroll
            for (int db = 0; db < 4; db++)
                ldsm2(vb[db][0], vb[db][1], vcur + db * (8 * VT_STRIDE * 2) + c * 32);

#pragma unroll
            for (int qt = 0; qt < 2; qt++) {
                float S0[4] = {0.f, 0.f, 0.f, 0.f};
                float S1[4] = {0.f, 0.f, 0.f, 0.f};
#pragma unroll
                for (int kblk = 0; kblk < 2; kblk++) {
                    mma16h(S0, qa[qt][kblk][0], qa[qt][kblk][1], qa[qt][kblk][2], qa[qt][kblk][3],
                           kb[0][kblk][0], kb[0][kblk][1]);
                    mma16h(S1, qa[qt][kblk][0], qa[qt][kblk][1], qa[qt][kblk][2], qa[qt][kblk][3],
                           kb[1][kblk][0], kb[1][kblk][1]);
                }
                uint32_t a0 = ex2h2(packh(S0[0], S0[1]));
                uint32_t a1 = ex2h2(packh(S0[2], S0[3]));
                uint32_t a2 = ex2h2(packh(S1[0], S1[1]));
                uint32_t a3 = ex2h2(packh(S1[2], S1[3]));
                float lo, hi;
                unpackh2(lo, hi, hadd2(a0, a2));
                lsum[qt][0] += lo + hi;
                unpackh2(lo, hi, hadd2(a1, a3));
                lsum[qt][1] += lo + hi;
#pragma unroll
                for (int db = 0; db < 4; db++)
                    mma16h(Oc[qt][db], a0, a1, a2, a3, vb[db][0], vb[db][1]);
            }
        }
        buf = (buf + 1 == 3) ? 0 : buf + 1;
    }

#pragma unroll
    for (int qt = 0; qt < 2; qt++)
#pragma unroll
        for (int r = 0; r < 2; r++) {
            float v = lsum[qt][r];
            v += __shfl_xor_sync(0xffffffffu, v, 1);
            v += __shfl_xor_sync(0xffffffffu, v, 2);
            lsum[qt][r] = 1.f / v;
        }

    float* Ot = reinterpret_cast<float*>(dsm);
    const int d = t >> 3, qoff = (t & 7) * 16;
#pragma unroll
    for (int qt = 0; qt < 2; qt++) {
        __syncthreads();
#pragma unroll
        for (int db = 0; db < 4; db++) {
            int dd = 8 * db + 2 * tg;
            Ot[dd * OT_STRIDE + m0 + g]           = Oc[qt][db][0] * lsum[qt][0];
            Ot[(dd + 1) * OT_STRIDE + m0 + g]     = Oc[qt][db][1] * lsum[qt][0];
            Ot[dd * OT_STRIDE + m0 + 8 + g]       = Oc[qt][db][2] * lsum[qt][1];
            Ot[(dd + 1) * OT_STRIDE + m0 + 8 + g] = Oc[qt][db][3] * lsum[qt][1];
        }
        __syncthreads();
        __half* ob = g_att + ((size_t)(bh >> 2) * CH + (bh & 3) * DIMH) * NTOK + q0 + 128 * qt;
        float4 v0 = *reinterpret_cast<float4*>(&Ot[d * OT_STRIDE + qoff]);
        float4 v1 = *reinterpret_cast<float4*>(&Ot[d * OT_STRIDE + qoff + 4]);
        float4 v2 = *reinterpret_cast<float4*>(&Ot[d * OT_STRIDE + qoff + 8]);
        float4 v3 = *reinterpret_cast<float4*>(&Ot[d * OT_STRIDE + qoff + 12]);
        uint4 o0 = make_uint4(packh(v0.x, v0.y), packh(v0.z, v0.w),
                              packh(v1.x, v1.y), packh(v1.z, v1.w));
        uint4 o1 = make_uint4(packh(v2.x, v2.y), packh(v2.z, v2.w),
                              packh(v3.x, v3.y), packh(v3.z, v3.w));
        *reinterpret_cast<uint4*>(ob + (size_t)d * NTOK + qoff)     = o0;
        *reinterpret_cast<uint4*>(ob + (size_t)d * NTOK + qoff + 8) = o1;
    }
}

// ---------------------------------------------------------------------------
// Kernel C: fp16 2-pass split proj; ALL staging via cp.async (unchanged).
// TILE_N=64, grid (64, 4), block 256, occ 2.
// ---------------------------------------------------------------------------
#define PROJ_SMEM ((2 * 128 * QW_STR + 128 * QX_STR) * 2)  // 88064 B

__global__ __launch_bounds__(256, 2) void proj_kernel(const float* __restrict__ bias,
                                                      float* __restrict__ out) {
    extern __shared__ __half hsm[];
    __half* Wh = hsm;
    __half* Wl = hsm + 128 * QW_STR;
    __half* Xh = hsm + 2 * 128 * QW_STR;

    const int t = threadIdx.x;
    const int lane = t & 31, wid = t >> 5;
    const int g = lane >> 2, tg = lane & 3;
    const int rr = lane & 15;
    const int m0 = wid * 16;
    const int b = blockIdx.y;
    const int n0 = blockIdx.x * 64;

    const __half* ab = g_att + (size_t)b * CH * NTOK;
    const uint32_t xh_u0 = smem_u32(Xh);
    const uint32_t wh_u = smem_u32(Wh);
    const uint32_t wl_u = smem_u32(Wl);
    const int wrow = t >> 4, wc = t & 15;
#pragma unroll
    for (int i = 0; i < 4; i++) {
        int e = t + i * 256, row = e >> 3, c = e & 7;
        cpa16(xh_u0 + (row * QX_STR + c * 8) * 2u, ab + (size_t)row * NTOK + n0 + c * 8);
    }
#pragma unroll
    for (int i = 0; i < 8; i++) {
        cpa16(wh_u + ((wrow + 16 * i) * QW_STR + wc * 8) * 2u,
              g_pwh + (size_t)(wrow + 16 * i) * 128 + wc * 8);
        cpa16(wl_u + ((wrow + 16 * i) * QW_STR + wc * 8) * 2u,
              g_pwl + (size_t)(wrow + 16 * i) * 128 + wc * 8);
    }
    CP_COMMIT();
    CP_WAIT0();
    __syncthreads();

    float Sc[8][4];
#pragma unroll
    for (int nb = 0; nb < 8; nb++)
        Sc[nb][0] = Sc[nb][1] = Sc[nb][2] = Sc[nb][3] = 0.f;

    const int o = m0 + g, o2 = m0 + 8 + g;
    const uint32_t xh_u = xh_u0 + rr * (QX_STR * 2);

#pragma unroll
    for (int kblk = 0; kblk < 8; kblk++) {
        const int kc = 16 * kblk + 2 * tg;
        uint32_t ah0 = *reinterpret_cast<const uint32_t*>(&Wh[o  * QW_STR + kc]);
        uint32_t ah1 = *reinterpret_cast<const uint32_t*>(&Wh[o2 * QW_STR + kc]);
        uint32_t ah2 = *reinterpret_cast<const uint32_t*>(&Wh[o  * QW_STR + kc + 8]);
        uint32_t ah3 = *reinterpret_cast<const uint32_t*>(&Wh[o2 * QW_STR + kc + 8]);
        uint32_t al0 = *reinterpret_cast<const uint32_t*>(&Wl[o  * QW_STR + kc]);
        uint32_t al1 = *reinterpret_cast<const uint32_t*>(&Wl[o2 * QW_STR + kc]);
        uint32_t al2 = *reinterpret_cast<const uint32_t*>(&Wl[o  * QW_STR + kc + 8]);
        uint32_t al3 = *reinterpret_cast<const uint32_t*>(&Wl[o2 * QW_STR + kc + 8]);
#pragma unroll
        for (int nb = 0; nb < 8; nb++) {
            uint32_t bh0, bh1;
            ldsm2t(bh0, bh1, xh_u + kblk * (16 * QX_STR * 2) + nb * 16);
            mma16h(Sc[nb], ah0, ah1, ah2, ah3, bh0, bh1);
            mma16h(Sc[nb], al0, al1, al2, al3, bh0, bh1);
        }
    }

    const float bv0 = bias[o], bv2 = bias[o2];
    float* r0 = out + ((size_t)b * CH + o)  * NTOK;
    float* r2 = out + ((size_t)b * CH + o2) * NTOK;
#pragma unroll
    for (int nb = 0; nb < 8; nb++) {
        int n = n0 + 8 * nb + 2 * tg;
        *reinterpret_cast<float2*>(&r0[n]) = make_float2(Sc[nb][0] + bv0, Sc[nb][1] + bv0);
        *reinterpret_cast<float2*>(&r2[n]) = make_float2(Sc[nb][2] + bv2, Sc[nb][3] + bv2);
    }
}

// ---------------------------------------------------------------------------
extern "C" void kernel_launch(void* const* d_in, const int* in_sizes, int n_in,
                              void* d_out, int out_size) {
    const float* x     = (const float*)d_in[0]; // [4,128,64,64]
    const float* w_qkv = (const float*)d_in[1]; // [384,128]
    const float* w_out = (const float*)d_in[2]; // [128,128]
    const float* b_out = (const float*)d_in[3]; // [128]
    float* out = (float*)d_out;                 // [4,128,64,64]

    cudaFuncSetAttribute(qkv_kernel,  cudaFuncAttributeMaxDynamicSharedMemorySize, QKV_SMEM);
    cudaFuncSetAttribute(attn_kernel, cudaFuncAttributeMaxDynamicSharedMemorySize, ATT_SMEM);
    cudaFuncSetAttribute(proj_kernel, cudaFuncAttributeMaxDynamicSharedMemorySize, PROJ_SMEM);

    w16_kernel<<<2112, 256>>>(x, w_qkv, w_out);
    qkv_kernel<<<dim3(64, BATCH), 256, QKV_SMEM>>>();
    attn_kernel<<<dim3(16, 16), 256, ATT_SMEM>>>();
    proj_kernel<<<dim3(64, BATCH), 256, PROJ_SMEM>>>(b_out, out);
}

// round 17
// speedup vs baseline: 1.0019x; 1.0019x over previous
#include <cuda_runtime.h>
#include <cuda_fp16.h>
#include <cstdint>

#define HEADS 4
#define DIMH  32
#define NTOK  4096
#define CH    128
#define BATCH 4

// Scratch (allocation is forbidden in kernel_launch).
__device__ __align__(16) __half g_q[(size_t)BATCH * HEADS * NTOK * DIMH];  // [bh][n][32], pre-scaled dimh^-.5*log2e
__device__ __align__(16) __half g_k[(size_t)BATCH * HEADS * NTOK * DIMH];  // [bh][n][32]
__device__ __align__(16) __half g_v[(size_t)BATCH * HEADS * DIMH * NTOK];  // [bh][32][n] d-major
__device__ __align__(16) __half g_att[(size_t)BATCH * CH * NTOK];          // [b][128][n] d-major fp16
__device__ __align__(16) __half g_x[(size_t)BATCH * CH * NTOK];            // x in fp16
// Pre-converted weights (filled by w16_kernel each launch).
__device__ __align__(16) __half g_wqh[3 * CH * CH];   // w_qkv fp16 hi (q rows pre-scaled)
__device__ __align__(16) __half g_wvl[CH * CH];       // w_qkv V-group fp16 residual
__device__ __align__(16) __half g_pwh[CH * CH];       // w_out fp16 hi
__device__ __align__(16) __half g_pwl[CH * CH];       // w_out fp16 residual

// ---------------------------------------------------------------------------
__device__ __forceinline__ uint32_t packh(float lo, float hi) {
    uint32_t r; asm("cvt.rn.f16x2.f32 %0, %1, %2;" : "=r"(r) : "f"(hi), "f"(lo)); return r;
}
__device__ __forceinline__ uint32_t ex2h2(uint32_t x) {
    uint32_t y; asm("ex2.approx.f16x2 %0, %1;" : "=r"(y) : "r"(x)); return y;
}
__device__ __forceinline__ uint32_t hadd2(uint32_t a, uint32_t b) {
    uint32_t y; asm("add.rn.f16x2 %0, %1, %2;" : "=r"(y) : "r"(a), "r"(b)); return y;
}
__device__ __forceinline__ void unpackh2(float& lo, float& hi, uint32_t x) {
    asm("{.reg .f16 l,h; mov.b32 {l,h}, %2; cvt.f32.f16 %0, l; cvt.f32.f16 %1, h;}"
        : "=f"(lo), "=f"(hi) : "r"(x));
}
__device__ __forceinline__ uint32_t pack2h(__half a, __half b) {
    return (uint32_t)__half_as_ushort(a) | ((uint32_t)__half_as_ushort(b) << 16);
}
__device__ __forceinline__ uint32_t smem_u32(const void* p) {
    uint32_t a;
    asm("{ .reg .u64 t; cvta.to.shared.u64 t, %1; cvt.u32.u64 %0, t; }" : "=r"(a) : "l"(p));
    return a;
}
__device__ __forceinline__ void cpa16(uint32_t dst, const void* src) {
    asm volatile("cp.async.ca.shared.global [%0], [%1], 16;" :: "r"(dst), "l"(src));
}
#define CP_COMMIT() asm volatile("cp.async.commit_group;" ::: "memory")
#define CP_WAIT0()  asm volatile("cp.async.wait_group 0;" ::: "memory")
#define CP_WAIT1()  asm volatile("cp.async.wait_group 1;" ::: "memory")
__device__ __forceinline__ void ldsm2(uint32_t& a, uint32_t& b, uint32_t addr) {
    asm volatile("ldmatrix.sync.aligned.m8n8.x2.shared.b16 {%0,%1}, [%2];"
                 : "=r"(a), "=r"(b) : "r"(addr));
}
__device__ __forceinline__ void ldsm2t(uint32_t& a, uint32_t& b, uint32_t addr) {
    asm volatile("ldmatrix.sync.aligned.m8n8.x2.trans.shared.b16 {%0,%1}, [%2];"
                 : "=r"(a), "=r"(b) : "r"(addr));
}
// D += A*B, fp16 m16n8k16, fp32 accum
__device__ __forceinline__ void mma16h(float c[4], uint32_t a0, uint32_t a1,
                                       uint32_t a2, uint32_t a3,
                                       uint32_t b0, uint32_t b1) {
    asm volatile(
        "mma.sync.aligned.m16n8k16.row.col.f32.f16.f16.f32 "
        "{%0,%1,%2,%3}, {%4,%5,%6,%7}, {%8,%9}, {%0,%1,%2,%3};"
        : "+f"(c[0]), "+f"(c[1]), "+f"(c[2]), "+f"(c[3])
        : "r"(a0), "r"(a1), "r"(a2), "r"(a3), "r"(b0), "r"(b1));
}

// ---------------------------------------------------------------------------
// Kernel W: one-time conversions (unchanged). grid (2112), block 256.
// ---------------------------------------------------------------------------
__global__ __launch_bounds__(256) void w16_kernel(const float* __restrict__ x,
                                                  const float* __restrict__ wqkv,
                                                  const float* __restrict__ wout) {
    const int idx = blockIdx.x * 256 + threadIdx.x;
    const float QSCALE = 0.17677669529663687f * 1.4426950408889634f;
    if (idx < 12288) {
        float4 v = *reinterpret_cast<const float4*>(wqkv + (size_t)idx * 4);
        const float s = (idx < 4096) ? QSCALE : 1.0f;
        __half h0 = __float2half(v.x * s), h1 = __float2half(v.y * s);
        __half h2 = __float2half(v.z * s), h3 = __float2half(v.w * s);
        *reinterpret_cast<uint2*>(&g_wqh[(size_t)idx * 4]) =
            make_uint2(pack2h(h0, h1), pack2h(h2, h3));
        if (idx >= 8192) {
            __half l0 = __float2half(v.x - __half2float(h0));
            __half l1 = __float2half(v.y - __half2float(h1));
            __half l2 = __float2half(v.z - __half2float(h2));
            __half l3 = __float2half(v.w - __half2float(h3));
            *reinterpret_cast<uint2*>(&g_wvl[(size_t)(idx - 8192) * 4]) =
                make_uint2(pack2h(l0, l1), pack2h(l2, l3));
        }
    } else if (idx < 16384) {
        const int j = idx - 12288;
        float4 v = *reinterpret_cast<const float4*>(wout + (size_t)j * 4);
        __half h0 = __float2half(v.x), h1 = __float2half(v.y);
        __half h2 = __float2half(v.z), h3 = __float2half(v.w);
        *reinterpret_cast<uint2*>(&g_pwh[(size_t)j * 4]) =
            make_uint2(pack2h(h0, h1), pack2h(h2, h3));
        __half l0 = __float2half(v.x - __half2float(h0));
        __half l1 = __float2half(v.y - __half2float(h1));
        __half l2 = __float2half(v.z - __half2float(h2));
        __half l3 = __float2half(v.w - __half2float(h3));
        *reinterpret_cast<uint2*>(&g_pwl[(size_t)j * 4]) =
            make_uint2(pack2h(l0, l1), pack2h(l2, l3));
    } else {
        const int j = idx - 16384;
        float4 v = *reinterpret_cast<const float4*>(x + (size_t)j * 4);
        *reinterpret_cast<uint2*>(&g_x[(size_t)j * 4]) =
            make_uint2(packh(v.x, v.y), packh(v.z, v.w));
    }
}

// ---------------------------------------------------------------------------
// Kernel A: fp16 tensor qkv, TILE_N=128 (single wave, W staged once/CTA).
// grid (32, 4), block 256, occ 2. All staging cp.async.
// ---------------------------------------------------------------------------
#define QW_STR 136
#define QX_STR 136
#define GEMM_SMEM (3 * 128 * QW_STR * 2)   // 104448 B

__global__ __launch_bounds__(256, 2) void qkv_kernel() {
    extern __shared__ __half hsm[];
    __half* Wh = hsm;
    __half* Wl = hsm + 128 * QW_STR;
    __half* Xh = hsm + 2 * 128 * QW_STR;

    const int t = threadIdx.x;
    const int lane = t & 31, wid = t >> 5;
    const int g = lane >> 2, tg = lane & 3;
    const int rr = lane & 15;
    const int m0 = wid * 16;
    const int b = blockIdx.y;
    const int n0 = blockIdx.x * 128;

    const uint32_t wh_u = smem_u32(Wh);
    const uint32_t wl_u = smem_u32(Wl);
    const uint32_t xh_u0 = smem_u32(Xh);
    const int wrow = t >> 4, wc = t & 15;

    // Prologue: X tile [128 c][128 n] (8/thread) + W group 0 (8/thread).
    const __half* xb = g_x + (size_t)b * CH * NTOK;
#pragma unroll
    for (int i = 0; i < 8; i++) {
        int e = t + i * 256, row = e >> 4, c = e & 15;
        cpa16(xh_u0 + (row * QX_STR + c * 8) * 2u, xb + (size_t)row * NTOK + n0 + c * 8);
    }
#pragma unroll
    for (int i = 0; i < 8; i++)
        cpa16(wh_u + ((wrow + 16 * i) * QW_STR + wc * 8) * 2u,
              g_wqh + (size_t)(wrow + 16 * i) * 128 + wc * 8);
    CP_COMMIT();

    const int o = m0 + g, o2 = m0 + 8 + g;
    const uint32_t xh_u = xh_u0 + rr * (QX_STR * 2);

    for (int grp = 0; grp < 3; grp++) {
        CP_WAIT0();
        __syncthreads();   // W[grp] + X ready

        float Sc[16][4];
#pragma unroll
        for (int nb = 0; nb < 16; nb++)
            Sc[nb][0] = Sc[nb][1] = Sc[nb][2] = Sc[nb][3] = 0.f;

#pragma unroll
        for (int kblk = 0; kblk < 8; kblk++) {
            const int kc = 16 * kblk + 2 * tg;
            uint32_t ah0 = *reinterpret_cast<const uint32_t*>(&Wh[o  * QW_STR + kc]);
            uint32_t ah1 = *reinterpret_cast<const uint32_t*>(&Wh[o2 * QW_STR + kc]);
            uint32_t ah2 = *reinterpret_cast<const uint32_t*>(&Wh[o  * QW_STR + kc + 8]);
            uint32_t ah3 = *reinterpret_cast<const uint32_t*>(&Wh[o2 * QW_STR + kc + 8]);
            uint32_t al0 = 0, al1 = 0, al2 = 0, al3 = 0;
            if (grp == 2) {
                al0 = *reinterpret_cast<const uint32_t*>(&Wl[o  * QW_STR + kc]);
                al1 = *reinterpret_cast<const uint32_t*>(&Wl[o2 * QW_STR + kc]);
                al2 = *reinterpret_cast<const uint32_t*>(&Wl[o  * QW_STR + kc + 8]);
                al3 = *reinterpret_cast<const uint32_t*>(&Wl[o2 * QW_STR + kc + 8]);
            }
#pragma unroll
            for (int nb = 0; nb < 16; nb++) {
                uint32_t b0, b1;
                ldsm2t(b0, b1, xh_u + kblk * (16 * QX_STR * 2) + nb * 16);
                mma16h(Sc[nb], ah0, ah1, ah2, ah3, b0, b1);
                if (grp == 2) mma16h(Sc[nb], al0, al1, al2, al3, b0, b1);
            }
        }

        __syncthreads();   // all warps done reading Wh/Wl
        if (grp < 2) {     // prefetch next group's W during output stores
            const __half* wg = g_wqh + (size_t)(grp + 1) * 128 * 128;
#pragma unroll
            for (int i = 0; i < 8; i++)
                cpa16(wh_u + ((wrow + 16 * i) * QW_STR + wc * 8) * 2u,
                      wg + (size_t)(wrow + 16 * i) * 128 + wc * 8);
            if (grp == 1) {
#pragma unroll
                for (int i = 0; i < 8; i++)
                    cpa16(wl_u + ((wrow + 16 * i) * QW_STR + wc * 8) * 2u,
                          g_wvl + (size_t)(wrow + 16 * i) * 128 + wc * 8);
            }
            CP_COMMIT();
        }

        if (grp < 2) {
            __half* dst = grp ? g_k : g_q;   // q pre-scaled via weights
            __half* r0 = dst + ((size_t)(b * HEADS + (o  >> 5)) * NTOK) * DIMH + (o  & 31);
            __half* r2 = dst + ((size_t)(b * HEADS + (o2 >> 5)) * NTOK) * DIMH + (o2 & 31);
#pragma unroll
            for (int nb = 0; nb < 16; nb++) {
                int n = n0 + 8 * nb + 2 * tg;
                r0[(size_t)n * DIMH]       = __float2half(Sc[nb][0]);
                r0[(size_t)(n + 1) * DIMH] = __float2half(Sc[nb][1]);
                r2[(size_t)n * DIMH]       = __float2half(Sc[nb][2]);
                r2[(size_t)(n + 1) * DIMH] = __float2half(Sc[nb][3]);
            }
        } else {
            __half* v0 = g_v + ((size_t)(b * HEADS + (o  >> 5)) * DIMH + (o  & 31)) * NTOK;
            __half* v2 = g_v + ((size_t)(b * HEADS + (o2 >> 5)) * DIMH + (o2 & 31)) * NTOK;
#pragma unroll
            for (int nb = 0; nb < 16; nb++) {
                int n = n0 + 8 * nb + 2 * tg;
                *reinterpret_cast<uint32_t*>(&v0[n]) = packh(Sc[nb][0], Sc[nb][1]);
                *reinterpret_cast<uint32_t*>(&v2[n]) = packh(Sc[nb][2], Sc[nb][3]);
            }
        }
    }
}

// ---------------------------------------------------------------------------
// Kernel B: fp16 flash attention, triple-buffer ring (unchanged from r15).
// grid (16, 16), block 256, occ 2.
// ---------------------------------------------------------------------------
#define QK_STRIDE 40
#define VT_STRIDE 136
#define OT_STRIDE 132
#define QT_BYTES  (128 * QK_STRIDE * 2)
#define QS_BYTES  (2 * QT_BYTES)
#define KS_BYTES  (128 * QK_STRIDE * 2)
#define VT_BYTES  (DIMH * VT_STRIDE * 2)
#define ATT_SMEM  (QS_BYTES + 3 * KS_BYTES + 3 * VT_BYTES)  // 77312

__global__ __launch_bounds__(256, 2) void attn_kernel() {
    extern __shared__ __align__(16) char dsm[];
    __half* Qs = reinterpret_cast<__half*>(dsm);
    __half* Ks = reinterpret_cast<__half*>(dsm + QS_BYTES);
    __half* Vt = reinterpret_cast<__half*>(dsm + QS_BYTES + 3 * KS_BYTES);

    const int t = threadIdx.x;
    const int lane = t & 31, wid = t >> 5;
    const int g = lane >> 2, tg = lane & 3;
    const int rr = lane & 15;
    const int m0 = wid * 16;
    const int bh = blockIdx.y;
    const int q0 = blockIdx.x << 8;

    const __half* qg = g_q + ((size_t)bh * NTOK + q0) * DIMH;
    const __half* kg = g_k + (size_t)bh * NTOK * DIMH;
    const __half* vg = g_v + (size_t)bh * DIMH * NTOK;

    const int kr0 = t >> 2, kc0 = t & 3;
    const int kr1 = (t + 256) >> 2, kc1 = t & 3;
    const int svr = t >> 4, svc = t & 15;
    const uint32_t ks_u = smem_u32(Ks);
    const uint32_t vt_u = smem_u32(Vt);
    const uint32_t kfrag = ks_u + (rr & 7) * (QK_STRIDE * 2) + (rr >> 3) * 16;
    const uint32_t vfrag = vt_u + (rr & 7) * (VT_STRIDE * 2) + (rr >> 3) * 16;

    cpa16(ks_u + (kr0 * QK_STRIDE + kc0 * 8) * 2u, kg + (size_t)kr0 * DIMH + kc0 * 8);
    cpa16(ks_u + (kr1 * QK_STRIDE + kc1 * 8) * 2u, kg + (size_t)kr1 * DIMH + kc1 * 8);
#pragma unroll
    for (int k2 = 0; k2 < 2; k2++)
        cpa16(vt_u + ((svr + 16 * k2) * VT_STRIDE + svc * 8) * 2u,
              vg + (size_t)(svr + 16 * k2) * NTOK + svc * 8);
    CP_COMMIT();

#pragma unroll
    for (int i = 0; i < 4; i++) {
        int idx = t + i * 256, row = idx >> 2, c = idx & 3;
        *reinterpret_cast<uint4*>(&Qs[row * QK_STRIDE + c * 8]) =
            *reinterpret_cast<const uint4*>(qg + (size_t)row * DIMH + c * 8);
    }
    __syncthreads();

    uint32_t qa[2][2][4];
#pragma unroll
    for (int qt = 0; qt < 2; qt++)
#pragma unroll
        for (int kblk = 0; kblk < 2; kblk++) {
            const __half* r0 = &Qs[(128 * qt + m0 + g)     * QK_STRIDE + 16 * kblk + 2 * tg];
            const __half* r1 = &Qs[(128 * qt + m0 + 8 + g) * QK_STRIDE + 16 * kblk + 2 * tg];
            qa[qt][kblk][0] = *reinterpret_cast<const uint32_t*>(r0);
            qa[qt][kblk][1] = *reinterpret_cast<const uint32_t*>(r1);
            qa[qt][kblk][2] = *reinterpret_cast<const uint32_t*>(r0 + 8);
            qa[qt][kblk][3] = *reinterpret_cast<const uint32_t*>(r1 + 8);
        }

    float Oc[2][4][4];
#pragma unroll
    for (int qt = 0; qt < 2; qt++)
#pragma unroll
        for (int db = 0; db < 4; db++)
#pragma unroll
            for (int i = 0; i < 4; i++) Oc[qt][db][i] = 0.f;
    float lsum[2][2] = {{0.f, 0.f}, {0.f, 0.f}};
    int buf = 0;

    for (int tile = 0; tile < 32; tile++) {
        if (tile < 31) {
            const int jn = (tile + 1) << 7;
            const int nb3 = (buf + 1 == 3) ? 0 : buf + 1;
            const uint32_t kd = ks_u + nb3 * KS_BYTES;
            const uint32_t vd = vt_u + nb3 * VT_BYTES;
            cpa16(kd + (kr0 * QK_STRIDE + kc0 * 8) * 2u, kg + (size_t)(jn + kr0) * DIMH + kc0 * 8);
            cpa16(kd + (kr1 * QK_STRIDE + kc1 * 8) * 2u, kg + (size_t)(jn + kr1) * DIMH + kc1 * 8);
#pragma unroll
            for (int k2 = 0; k2 < 2; k2++)
                cpa16(vd + ((svr + 16 * k2) * VT_STRIDE + svc * 8) * 2u,
                      vg + (size_t)(svr + 16 * k2) * NTOK + jn + svc * 8);
        }
        CP_COMMIT();
        CP_WAIT1();
        __syncthreads();

        const uint32_t kcur = kfrag + buf * KS_BYTES;
        const uint32_t vcur = vfrag + buf * VT_BYTES;

#pragma unroll
        for (int c = 0; c < 8; c++) {
            const int nb0 = 2 * c, nb1 = nb0 + 1;
            uint32_t kb[2][2][2];
#pragma unroll
            for (int kblk = 0; kblk < 2; kblk++) {
                ldsm2(kb[0][kblk][0], kb[0][kblk][1], kcur + nb0 * (8 * QK_STRIDE * 2) + kblk * 32);
                ldsm2(kb[1][kblk][0], kb[1][kblk][1], kcur + nb1 * (8 * QK_STRIDE * 2) + kblk * 32);
            }
            uint32_t vb[4][2];
#pragma unroll
            for (int db = 0; db < 4; db++)
                ldsm2(vb[db][0], vb[db][1], vcur + db * (8 * VT_STRIDE * 2) + c * 32);

#pragma unroll
            for (int qt = 0; qt < 2; qt++) {
                float S0[4] = {0.f, 0.f, 0.f, 0.f};
                float S1[4] = {0.f, 0.f, 0.f, 0.f};
#pragma unroll
                for (int kblk = 0; kblk < 2; kblk++) {
                    mma16h(S0, qa[qt][kblk][0], qa[qt][kblk][1], qa[qt][kblk][2], qa[qt][kblk][3],
                           kb[0][kblk][0], kb[0][kblk][1]);
                    mma16h(S1, qa[qt][kblk][0], qa[qt][kblk][1], qa[qt][kblk][2], qa[qt][kblk][3],
                           kb[1][kblk][0], kb[1][kblk][1]);
                }
                uint32_t a0 = ex2h2(packh(S0[0], S0[1]));
                uint32_t a1 = ex2h2(packh(S0[2], S0[3]));
                uint32_t a2 = ex2h2(packh(S1[0], S1[1]));
                uint32_t a3 = ex2h2(packh(S1[2], S1[3]));
                float lo, hi;
                unpackh2(lo, hi, hadd2(a0, a2));
                lsum[qt][0] += lo + hi;
                unpackh2(lo, hi, hadd2(a1, a3));
                lsum[qt][1] += lo + hi;
#pragma unroll
                for (int db = 0; db < 4; db++)
                    mma16h(Oc[qt][db], a0, a1, a2, a3, vb[db][0], vb[db][1]);
            }
        }
        buf = (buf + 1 == 3) ? 0 : buf + 1;
    }

#pragma unroll
    for (int qt = 0; qt < 2; qt++)
#pragma unroll
        for (int r = 0; r < 2; r++) {
            float v = lsum[qt][r];
            v += __shfl_xor_sync(0xffffffffu, v, 1);
            v += __shfl_xor_sync(0xffffffffu, v, 2);
            lsum[qt][r] = 1.f / v;
        }

    float* Ot = reinterpret_cast<float*>(dsm);
    const int d = t >> 3, qoff = (t & 7) * 16;
#pragma unroll
    for (int qt = 0; qt < 2; qt++) {
        __syncthreads();
#pragma unroll
        for (int db = 0; db < 4; db++) {
            int dd = 8 * db + 2 * tg;
            Ot[dd * OT_STRIDE + m0 + g]           = Oc[qt][db][0] * lsum[qt][0];
            Ot[(dd + 1) * OT_STRIDE + m0 + g]     = Oc[qt][db][1] * lsum[qt][0];
            Ot[dd * OT_STRIDE + m0 + 8 + g]       = Oc[qt][db][2] * lsum[qt][1];
            Ot[(dd + 1) * OT_STRIDE + m0 + 8 + g] = Oc[qt][db][3] * lsum[qt][1];
        }
        __syncthreads();
        __half* ob = g_att + ((size_t)(bh >> 2) * CH + (bh & 3) * DIMH) * NTOK + q0 + 128 * qt;
        float4 v0 = *reinterpret_cast<float4*>(&Ot[d * OT_STRIDE + qoff]);
        float4 v1 = *reinterpret_cast<float4*>(&Ot[d * OT_STRIDE + qoff + 4]);
        float4 v2 = *reinterpret_cast<float4*>(&Ot[d * OT_STRIDE + qoff + 8]);
        float4 v3 = *reinterpret_cast<float4*>(&Ot[d * OT_STRIDE + qoff + 12]);
        uint4 o0 = make_uint4(packh(v0.x, v0.y), packh(v0.z, v0.w),
                              packh(v1.x, v1.y), packh(v1.z, v1.w));
        uint4 o1 = make_uint4(packh(v2.x, v2.y), packh(v2.z, v2.w),
                              packh(v3.x, v3.y), packh(v3.z, v3.w));
        *reinterpret_cast<uint4*>(ob + (size_t)d * NTOK + qoff)     = o0;
        *reinterpret_cast<uint4*>(ob + (size_t)d * NTOK + qoff + 8) = o1;
    }
}

// ---------------------------------------------------------------------------
// Kernel C: fp16 2-pass split proj, TILE_N=128 (single wave). grid (32, 4).
// ---------------------------------------------------------------------------
__global__ __launch_bounds__(256, 2) void proj_kernel(const float* __restrict__ bias,
                                                      float* __restrict__ out) {
    extern __shared__ __half hsm[];
    __half* Wh = hsm;
    __half* Wl = hsm + 128 * QW_STR;
    __half* Xh = hsm + 2 * 128 * QW_STR;

    const int t = threadIdx.x;
    const int lane = t & 31, wid = t >> 5;
    const int g = lane >> 2, tg = lane & 3;
    const int rr = lane & 15;
    const int m0 = wid * 16;
    const int b = blockIdx.y;
    const int n0 = blockIdx.x * 128;

    const __half* ab = g_att + (size_t)b * CH * NTOK;
    const uint32_t xh_u0 = smem_u32(Xh);
    const uint32_t wh_u = smem_u32(Wh);
    const uint32_t wl_u = smem_u32(Wl);
    const int wrow = t >> 4, wc = t & 15;
#pragma unroll
    for (int i = 0; i < 8; i++) {
        int e = t + i * 256, row = e >> 4, c = e & 15;
        cpa16(xh_u0 + (row * QX_STR + c * 8) * 2u, ab + (size_t)row * NTOK + n0 + c * 8);
    }
#pragma unroll
    for (int i = 0; i < 8; i++) {
        cpa16(wh_u + ((wrow + 16 * i) * QW_STR + wc * 8) * 2u,
              g_pwh + (size_t)(wrow + 16 * i) * 128 + wc * 8);
        cpa16(wl_u + ((wrow + 16 * i) * QW_STR + wc * 8) * 2u,
              g_pwl + (size_t)(wrow + 16 * i) * 128 + wc * 8);
    }
    CP_COMMIT();
    CP_WAIT0();
    __syncthreads();

    float Sc[16][4];
#pragma unroll
    for (int nb = 0; nb < 16; nb++)
        Sc[nb][0] = Sc[nb][1] = Sc[nb][2] = Sc[nb][3] = 0.f;

    const int o = m0 + g, o2 = m0 + 8 + g;
    const uint32_t xh_u = xh_u0 + rr * (QX_STR * 2);

#pragma unroll
    for (int kblk = 0; kblk < 8; kblk++) {
        const int kc = 16 * kblk + 2 * tg;
        uint32_t ah0 = *reinterpret_cast<const uint32_t*>(&Wh[o  * QW_STR + kc]);
        uint32_t ah1 = *reinterpret_cast<const uint32_t*>(&Wh[o2 * QW_STR + kc]);
        uint32_t ah2 = *reinterpret_cast<const uint32_t*>(&Wh[o  * QW_STR + kc + 8]);
        uint32_t ah3 = *reinterpret_cast<const uint32_t*>(&Wh[o2 * QW_STR + kc + 8]);
        uint32_t al0 = *reinterpret_cast<const uint32_t*>(&Wl[o  * QW_STR + kc]);
        uint32_t al1 = *reinterpret_cast<const uint32_t*>(&Wl[o2 * QW_STR + kc]);
        uint32_t al2 = *reinterpret_cast<const uint32_t*>(&Wl[o  * QW_STR + kc + 8]);
        uint32_t al3 = *reinterpret_cast<const uint32_t*>(&Wl[o2 * QW_STR + kc + 8]);
#pragma unroll
        for (int nb = 0; nb < 16; nb++) {
            uint32_t bh0, bh1;
            ldsm2t(bh0, bh1, xh_u + kblk * (16 * QX_STR * 2) + nb * 16);
            mma16h(Sc[nb], ah0, ah1, ah2, ah3, bh0, bh1);
            mma16h(Sc[nb], al0, al1, al2, al3, bh0, bh1);
        }
    }

    const float bv0 = bias[o], bv2 = bias[o2];
    float* r0 = out + ((size_t)b * CH + o)  * NTOK;
    float* r2 = out + ((size_t)b * CH + o2) * NTOK;
#pragma unroll
    for (int nb = 0; nb < 16; nb++) {
        int n = n0 + 8 * nb + 2 * tg;
        *reinterpret_cast<float2*>(&r0[n]) = make_float2(Sc[nb][0] + bv0, Sc[nb][1] + bv0);
        *reinterpret_cast<float2*>(&r2[n]) = make_float2(Sc[nb][2] + bv2, Sc[nb][3] + bv2);
    }
}

// ---------------------------------------------------------------------------
extern "C" void kernel_launch(void* const* d_in, const int* in_sizes, int n_in,
                              void* d_out, int out_size) {
    const float* x     = (const float*)d_in[0]; // [4,128,64,64]
    const float* w_qkv = (const float*)d_in[1]; // [384,128]
    const float* w_out = (const float*)d_in[2]; // [128,128]
    const float* b_out = (const float*)d_in[3]; // [128]
    float* out = (float*)d_out;                 // [4,128,64,64]

    cudaFuncSetAttribute(qkv_kernel,  cudaFuncAttributeMaxDynamicSharedMemorySize, GEMM_SMEM);
    cudaFuncSetAttribute(attn_kernel, cudaFuncAttributeMaxDynamicSharedMemorySize, ATT_SMEM);
    cudaFuncSetAttribute(proj_kernel, cudaFuncAttributeMaxDynamicSharedMemorySize, GEMM_SMEM);

    w16_kernel<<<2112, 256>>>(x, w_qkv, w_out);
    qkv_kernel<<<dim3(32, BATCH), 256, GEMM_SMEM>>>();
    attn_kernel<<<dim3(16, 16), 256, ATT_SMEM>>>();
    proj_kernel<<<dim3(32, BATCH), 256, GEMM_SMEM>>>(b_out, out);
}